// round 14
// baseline (speedup 1.0000x reference)
#include <cuda_runtime.h>
#include <cuda_bf16.h>
#include <cstdint>

#define NB 64
#define NS 256
#define NI 256
#define NHH 512
#define N2H 1024
#define NM (NB*NS)
#define CS 64          // scan chunk size
#define NC (NS/CS)     // 4 chunks

// Scratch (static device arrays)
static __device__ float g_C  [(size_t)NM * N2H];        // x@W^T           64MB
static __device__ float g_KTP[(size_t)NB * NS * NHH];   // kt' traces      33MB
static __device__ float g_WQ [(size_t)NB * NS * NHH];   // wq[b][s][r]     33MB
static __device__ float g_G  [(size_t)NB * NS * NS];    // Gram[b][s][t]   16MB
static __device__ float g_BASE[(size_t)NB * NHH * CS];  // per-chunk base   8MB
static __device__ float g_SVS[NB*NHH], g_SVT[NB*NHH], g_SP[NB*NHH], g_SQ[NB*NHH];

__device__ __forceinline__ float fast_tanh(float x){
    float z = __expf(2.0f * x);
    return 1.0f - __fdividef(2.0f, z + 1.0f);
}
__device__ __forceinline__ float tanh_approx(float x){
    float r; asm("tanh.approx.f32 %0, %1;" : "=f"(r) : "f"(x)); return r;
}

#define ALPHA 0.9048374180359595f
#define DECAY 0.9512294245007140f
#define OMD   0.0487705754992860f
#define LRC   0.01f

// ===== HMMA helpers (pattern validated in R13 memgemm: rel_err unchanged) =====
#define MG_LD 40

__device__ __forceinline__ void mma_bf16(float c[4], uint32_t a0, uint32_t a1,
                                         uint32_t a2, uint32_t a3,
                                         uint32_t b0, uint32_t b1){
    asm volatile(
        "mma.sync.aligned.m16n8k16.row.col.f32.bf16.bf16.f32 "
        "{%0,%1,%2,%3}, {%4,%5,%6,%7}, {%8,%9}, {%0,%1,%2,%3};"
        : "+f"(c[0]), "+f"(c[1]), "+f"(c[2]), "+f"(c[3])
        : "r"(a0), "r"(a1), "r"(a2), "r"(a3), "r"(b0), "r"(b1));
}

// Shared 128x128-tile HMMA core: stages pre-split bf16 from smem arrays,
// runs 2x(ks=16) fragment loop with 3 error-compensated passes.
// Caller stages Ah/Al/Bh/Bl ([128][MG_LD] u16) per 32-wide k-chunk.
#define HMMA_FRAG_AND_MMA(Ah, Al, Bh, Bl, cacc, wm, wn, g, t)                        \
    _Pragma("unroll")                                                                 \
    for (int ks = 0; ks < 32; ks += 16){                                              \
        uint32_t ah[4][4], al[4][4];                                                  \
        _Pragma("unroll")                                                             \
        for (int mt=0; mt<4; mt++){                                                   \
            int row = (wm) + mt*16;                                                   \
            int o00 = (row + (g)    )*MG_LD + ks + 2*(t);                             \
            int o10 = (row + (g) + 8)*MG_LD + ks + 2*(t);                             \
            ah[mt][0] = *(const uint32_t*)&Ah[o00];                                   \
            ah[mt][1] = *(const uint32_t*)&Ah[o10];                                   \
            ah[mt][2] = *(const uint32_t*)&Ah[o00 + 8];                               \
            ah[mt][3] = *(const uint32_t*)&Ah[o10 + 8];                               \
            al[mt][0] = *(const uint32_t*)&Al[o00];                                   \
            al[mt][1] = *(const uint32_t*)&Al[o10];                                   \
            al[mt][2] = *(const uint32_t*)&Al[o00 + 8];                               \
            al[mt][3] = *(const uint32_t*)&Al[o10 + 8];                               \
        }                                                                             \
        uint32_t bh[4][2], bl[4][2];                                                  \
        _Pragma("unroll")                                                             \
        for (int nt=0; nt<4; nt++){                                                   \
            int n = (wn) + nt*8 + (g);                                                \
            int o = n*MG_LD + ks + 2*(t);                                             \
            bh[nt][0] = *(const uint32_t*)&Bh[o];                                     \
            bh[nt][1] = *(const uint32_t*)&Bh[o + 8];                                 \
            bl[nt][0] = *(const uint32_t*)&Bl[o];                                     \
            bl[nt][1] = *(const uint32_t*)&Bl[o + 8];                                 \
        }                                                                             \
        _Pragma("unroll")                                                             \
        for (int mt=0; mt<4; mt++)                                                    \
            _Pragma("unroll")                                                         \
            for (int nt=0; nt<4; nt++){                                               \
                mma_bf16(cacc[mt][nt], ah[mt][0],ah[mt][1],ah[mt][2],ah[mt][3], bh[nt][0],bh[nt][1]); \
                mma_bf16(cacc[mt][nt], ah[mt][0],ah[mt][1],ah[mt][2],ah[mt][3], bl[nt][0],bl[nt][1]); \
                mma_bf16(cacc[mt][nt], al[mt][0],al[mt][1],al[mt][2],al[mt][3], bh[nt][0],bh[nt][1]); \
            }                                                                         \
    }

__device__ __forceinline__ void split_store(unsigned short* H, unsigned short* L,
                                            int off, float v){
    __nv_bfloat16 h = __float2bfloat16(v);
    __nv_bfloat16 l = __float2bfloat16(v - __bfloat162float(h));
    H[off] = __bfloat16_as_ushort(h);
    L[off] = __bfloat16_as_ushort(l);
}

// ---------------------------------------------------------------------------
// Kernel 1: SGEMM on HMMA  C[m][n] = sum_k x[m][k]*W[n][k]
// 128x128 CTA tile, K=256. Operands k-contiguous -> stage with k fast.
// ---------------------------------------------------------------------------
__global__ __launch_bounds__(256) void sgemm_mma(const float* __restrict__ A,
                                                 const float* __restrict__ W)
{
    __shared__ unsigned short Ah[128*MG_LD], Al[128*MG_LD];
    __shared__ unsigned short Bh[128*MG_LD], Bl[128*MG_LD];
    const int tid = threadIdx.x;
    const int wid = tid >> 5, lane = tid & 31;
    const int g = lane >> 2, t = lane & 3;
    const int n0 = blockIdx.x * 128;
    const int m0 = blockIdx.y * 128;
    const int wm = (wid >> 2) * 64;
    const int wn = (wid & 3) * 32;

    float c[4][4][4];
    #pragma unroll
    for (int i=0;i<4;i++)
        #pragma unroll
        for (int j=0;j<4;j++)
            #pragma unroll
            for (int q=0;q<4;q++) c[i][j][q]=0.f;

    for (int k0 = 0; k0 < NI; k0 += 32){
        #pragma unroll
        for (int i = 0; i < 16; i++){
            int idx = tid + i*256;          // 4096: k fast (coalesced)
            int k = idx & 31, m = idx >> 5;
            split_store(Ah, Al, m*MG_LD + k, __ldg(A + (size_t)(m0+m)*NI + k0 + k));
            split_store(Bh, Bl, m*MG_LD + k, __ldg(W + (size_t)(n0+m)*NI + k0 + k));
        }
        __syncthreads();
        HMMA_FRAG_AND_MMA(Ah, Al, Bh, Bl, c, wm, wn, g, t)
        __syncthreads();
    }

    #pragma unroll
    for (int mt=0; mt<4; mt++){
        int row = m0 + wm + mt*16 + g;
        #pragma unroll
        for (int nt=0; nt<4; nt++){
            int n = n0 + wn + nt*8 + 2*t;
            float* o0 = g_C + (size_t)row*N2H + n;
            float* o1 = o0 + 8*N2H;
            o0[0] = c[mt][nt][0];  o0[1] = c[mt][nt][1];
            o1[0] = c[mt][nt][2];  o1[1] = c[mt][nt][3];
        }
    }
}

// ---------------------------------------------------------------------------
// Kernel 2: per-(b,h) sequential traces: keys = tanh(ks), kt' = d*kt' + key
// ---------------------------------------------------------------------------
__global__ __launch_bounds__(256) void tracek_kernel(float* __restrict__ keys_out)
{
    int gid = blockIdx.x*blockDim.x + threadIdx.x;
    int b = gid >> 9, h = gid & 511;
    const float* c = g_C + (size_t)b*NS*N2H + h;
    float* ko = keys_out + (size_t)b*NS*NHH + h;
    float* kp = g_KTP    + (size_t)b*NS*NHH + h;
    float ks = 0.f, kt = 0.f;
    #pragma unroll 8
    for (int t=0;t<NS;t++){
        ks = fmaf(ks, ALPHA, __ldg(c + (size_t)t*N2H));
        float k = fast_tanh(ks);
        ko[(size_t)t*NHH] = k;
        kt = fmaf(kt, DECAY, k);
        kp[(size_t)t*NHH] = kt;
    }
}

// ---------------------------------------------------------------------------
// Kernel 3: batched Gram on HMMA  G[b][s][t] = sum_h KTP[b][s][h]*keys[b][t][h]
// 3 tiles of 128x128 (lower-left s>t block never read), K=512. grid (3, 64).
// ---------------------------------------------------------------------------
__global__ __launch_bounds__(256) void gram_mma(const float* __restrict__ keys)
{
    __shared__ unsigned short Ah[128*MG_LD], Al[128*MG_LD];
    __shared__ unsigned short Bh[128*MG_LD], Bl[128*MG_LD];
    const int tid = threadIdx.x;
    const int wid = tid >> 5, lane = tid & 31;
    const int g = lane >> 2, t = lane & 3;
    const int b  = blockIdx.y;
    const int bi = blockIdx.x;           // 0,1,2 -> (bx,by) in {(0,0),(1,0),(1,1)}
    const int bx = (bi >= 1) ? 1 : 0;
    const int by = (bi == 2) ? 1 : 0;
    const int m0 = by * 128;
    const int n0 = bx * 128;
    const float* Ag = g_KTP + (size_t)b*NS*NHH;
    const float* Bg = keys  + (size_t)b*NS*NHH;
    const int wm = (wid >> 2) * 64;
    const int wn = (wid & 3) * 32;

    float c[4][4][4];
    #pragma unroll
    for (int i=0;i<4;i++)
        #pragma unroll
        for (int j=0;j<4;j++)
            #pragma unroll
            for (int q=0;q<4;q++) c[i][j][q]=0.f;

    for (int k0 = 0; k0 < NHH; k0 += 32){
        #pragma unroll
        for (int i = 0; i < 16; i++){
            int idx = tid + i*256;
            int k = idx & 31, m = idx >> 5;
            split_store(Ah, Al, m*MG_LD + k, __ldg(Ag + (size_t)(m0+m)*NHH + k0 + k));
            split_store(Bh, Bl, m*MG_LD + k, __ldg(Bg + (size_t)(n0+m)*NHH + k0 + k));
        }
        __syncthreads();
        HMMA_FRAG_AND_MMA(Ah, Al, Bh, Bl, c, wm, wn, g, t)
        __syncthreads();
    }

    float* Gout = g_G + (size_t)b*NS*NS;
    #pragma unroll
    for (int mt=0; mt<4; mt++){
        int row = m0 + wm + mt*16 + g;
        #pragma unroll
        for (int nt=0; nt<4; nt++){
            int n = n0 + wn + nt*8 + 2*t;
            float* o0 = Gout + (size_t)row*NS + n;
            float* o1 = o0 + 8*NS;
            o0[0] = c[mt][nt][0];  o0[1] = c[mt][nt][1];
            o1[0] = c[mt][nt][2];  o1[1] = c[mt][nt][3];
        }
    }
}

// ---------------------------------------------------------------------------
// Kernel 4: base GEMM for chunk c (c>=1)
// ---------------------------------------------------------------------------
__global__ __launch_bounds__(256) void basegemm_kernel(int c)
{
    __shared__ float As[32][64+1];
    __shared__ float Bs[32][64+1];
    const int tid = threadIdx.x;
    const int r0 = blockIdx.x * 64;
    const int b  = blockIdx.y;
    const int ty = tid >> 4, tx = tid & 15;
    const int tcol0 = c*CS;
    float acc[4][4];
    #pragma unroll
    for (int i=0;i<4;i++)
        #pragma unroll
        for (int j=0;j<4;j++) acc[i][j]=0.f;
    const int K = c*CS;
    for (int k0=0; k0<K; k0+=32){
        #pragma unroll
        for (int i=0;i<8;i++){
            int idx = tid + i*256;
            int kk = idx >> 6, col = idx & 63;
            As[kk][col] = g_WQ[((size_t)b*NS + k0+kk)*NHH + r0 + col];
            Bs[kk][col] = g_G [((size_t)b*NS + k0+kk)*NS  + tcol0 + col];
        }
        __syncthreads();
        #pragma unroll
        for (int kk=0;kk<32;kk++){
            float a[4], bb[4];
            #pragma unroll
            for (int i=0;i<4;i++) a[i]  = As[kk][ty*4+i];
            #pragma unroll
            for (int j=0;j<4;j++) bb[j] = Bs[kk][tx*4+j];
            #pragma unroll
            for (int i=0;i<4;i++)
                #pragma unroll
                for (int j=0;j<4;j++)
                    acc[i][j] = fmaf(a[i], bb[j], acc[i][j]);
        }
        __syncthreads();
    }
    #pragma unroll
    for (int i=0;i<4;i++)
        #pragma unroll
        for (int j=0;j<4;j++)
            g_BASE[((size_t)b*NHH + r0 + ty*4 + i)*CS + tx*4 + j] = acc[i][j];
}

// ---------------------------------------------------------------------------
// Kernel 5: chunk scan. Vectorized inner update: acc[j2] for j2<=j is dead
// after the read at step j, so updating the FULL row is legal -> 16x LDS.128
// + 64 FMA per step instead of 63 scalar LDS+FMA (scan was LDS-issue bound).
// ---------------------------------------------------------------------------
__global__ __launch_bounds__(256) void scan_kernel(int c, float* __restrict__ vals_out)
{
    __shared__ float Gs[CS][CS];        // unpadded: rows 256B-aligned for LDS.128
    const int tid = threadIdx.x;
    const int rh  = blockIdx.x;
    const int b   = blockIdx.y;
    const int r   = rh*256 + tid;

    for (int idx = tid; idx < CS*CS; idx += 256){
        int j = idx >> 6, j2 = idx & 63;
        Gs[j][j2] = g_G[((size_t)b*NS + c*CS + j)*NS + c*CS + j2];
    }
    __syncthreads();

    float vs, vt, P, Q;
    if (c == 0){ vs=0.f; vt=0.f; P=1.f; Q=LRC*OMD; }
    else { vs=g_SVS[b*NHH+r]; vt=g_SVT[b*NHH+r]; P=g_SP[b*NHH+r]; Q=g_SQ[b*NHH+r]; }

    float acc[CS];
    #pragma unroll
    for (int j=0;j<CS;j++) acc[j]=0.f;

    const float* ivp = g_C + ((size_t)(b*NS + c*CS))*N2H + NHH + r;
    const float* bp  = g_BASE + ((size_t)b*NHH + r)*CS;
    float* vp  = vals_out + ((size_t)(b*NS + c*CS))*NHH + r;
    float* wqp = g_WQ     + ((size_t)(b*NS + c*CS))*NHH + r;

    for (int j=0;j<CS;j++){
        float base = 0.f;
        if (c > 0) base = __ldg(bp + j);
        float iv = __ldg(ivp + (size_t)j*N2H);
        float dotraw = acc[j] + base;
        float dtrue = P * dotraw;
        vs = fmaf(vs, ALPHA, fmaf(0.2f, dtrue, iv));
        float v = tanh_approx(vs);
        vp[(size_t)j*NHH] = v;
        vt = fmaf(OMD, v, DECAY*vt);
        float e = LRC*vt*vt;
        P *= (1.0f - e);
        Q *= fmaf(e, fmaf(e, 1.0f + e, 1.0f), 1.0f);
        float wq = Q*vt;
        wqp[(size_t)j*NHH] = wq;
        // full-row vectorized update (entries <= j are dead; harmless)
        const float4* grow = (const float4*)(&Gs[j][0]);
        #pragma unroll
        for (int q=0;q<CS/4;q++){
            float4 gv = grow[q];
            acc[q*4+0] = fmaf(wq, gv.x, acc[q*4+0]);
            acc[q*4+1] = fmaf(wq, gv.y, acc[q*4+1]);
            acc[q*4+2] = fmaf(wq, gv.z, acc[q*4+2]);
            acc[q*4+3] = fmaf(wq, gv.w, acc[q*4+3]);
        }
    }

    g_SVS[b*NHH+r]=vs; g_SVT[b*NHH+r]=vt; g_SP[b*NHH+r]=P; g_SQ[b*NHH+r]=Q;
}

// ---------------------------------------------------------------------------
// Kernel 6: final mem GEMM on HMMA (unchanged from R13-passing version)
// ---------------------------------------------------------------------------
__global__ __launch_bounds__(256) void memgemm_mma(float* __restrict__ mem_out)
{
    __shared__ unsigned short Ah[128*MG_LD], Al[128*MG_LD];
    __shared__ unsigned short Bh[128*MG_LD], Bl[128*MG_LD];

    const int tid = threadIdx.x;
    const int wid = tid >> 5, lane = tid & 31;
    const int g = lane >> 2, t = lane & 3;
    const int n0 = blockIdx.x * 128;
    const int r0 = blockIdx.y * 128;
    const int b  = blockIdx.z;
    const int wm = (wid >> 2) * 64;
    const int wn = (wid & 3) * 32;

    float c[4][4][4];
    #pragma unroll
    for (int i=0;i<4;i++)
        #pragma unroll
        for (int j=0;j<4;j++)
            #pragma unroll
            for (int q=0;q<4;q++) c[i][j][q]=0.f;

    for (int k0 = 0; k0 < NS; k0 += 32){
        #pragma unroll
        for (int i = 0; i < 16; i++){
            int idx = tid + i*256;          // m fast (operands k-major)
            int m = idx & 127, k = idx >> 7;
            split_store(Ah, Al, m*MG_LD + k, __ldg(g_WQ  + ((size_t)b*NS + k0 + k)*NHH + r0 + m));
            split_store(Bh, Bl, m*MG_LD + k, __ldg(g_KTP + ((size_t)b*NS + k0 + k)*NHH + n0 + m));
        }
        __syncthreads();
        HMMA_FRAG_AND_MMA(Ah, Al, Bh, Bl, c, wm, wn, g, t)
        __syncthreads();
    }

    #pragma unroll
    for (int mt=0; mt<4; mt++){
        int row0g = r0 + wm + mt*16 + g;
        float p0 = g_SP[b*NHH + row0g];
        float p1 = g_SP[b*NHH + row0g + 8];
        #pragma unroll
        for (int nt=0; nt<4; nt++){
            int n = n0 + wn + nt*8 + 2*t;
            float* o0 = mem_out + ((size_t)b*NHH + row0g)*NHH + n;
            float* o1 = o0 + 8*NHH;
            o0[0] = c[mt][nt][0]*p0;  o0[1] = c[mt][nt][1]*p0;
            o1[0] = c[mt][nt][2]*p1;  o1[1] = c[mt][nt][3]*p1;
        }
    }
}

// ---------------------------------------------------------------------------
extern "C" void kernel_launch(void* const* d_in, const int* in_sizes, int n_in,
                              void* d_out, int out_size)
{
    const float* x = (const float*)d_in[0];   // [64,256,256]
    const float* W = (const float*)d_in[1];   // [1024,256]
    float* out = (float*)d_out;
    float* mem_out  = out;                                    // [64,512,512]
    float* keys_out = out + (size_t)NB*NHH*NHH;               // [64,256,512]
    float* vals_out = keys_out + (size_t)NB*NS*NHH;           // [64,256,512]

    sgemm_mma<<<dim3(N2H/128, NM/128), 256>>>(x, W);          // (8,128)
    tracek_kernel<<<(NB*NHH)/256, 256>>>(keys_out);
    gram_mma<<<dim3(3, NB), 256>>>(keys_out);
    for (int c = 0; c < NC; c++){
        if (c > 0) basegemm_kernel<<<dim3(NHH/64, NB), 256>>>(c);
        scan_kernel<<<dim3(2, NB), 256>>>(c, vals_out);
    }
    memgemm_mma<<<dim3(4, 4, NB), 256>>>(mem_out);
}

// round 15
// speedup vs baseline: 1.4007x; 1.4007x over previous
#include <cuda_runtime.h>
#include <cuda_bf16.h>
#include <cstdint>

#define NB 64
#define NS 256
#define NI 256
#define NHH 512
#define N2H 1024
#define NM (NB*NS)
#define CS 64          // scan chunk size
#define NC (NS/CS)     // 4 chunks

// Scratch (static device arrays)
static __device__ float g_C  [(size_t)NM * N2H];        // x@W^T           64MB
static __device__ float g_KTP[(size_t)NB * NS * NHH];   // kt' traces      33MB
static __device__ float g_WQ [(size_t)NB * NS * NHH];   // wq[b][s][r]     33MB
static __device__ float g_G  [(size_t)NB * NS * NS];    // Gram[b][s][t]   16MB
static __device__ float g_BASE[(size_t)NB * NHH * CS];  // per-chunk base   8MB
static __device__ float g_SVS[NB*NHH], g_SVT[NB*NHH], g_SP[NB*NHH], g_SQ[NB*NHH];

__device__ __forceinline__ float fast_tanh(float x){
    float z = __expf(2.0f * x);
    return 1.0f - __fdividef(2.0f, z + 1.0f);
}
__device__ __forceinline__ float tanh_approx(float x){
    float r; asm("tanh.approx.f32 %0, %1;" : "=f"(r) : "f"(x)); return r;
}

#define ALPHA 0.9048374180359595f
#define DECAY 0.9512294245007140f
#define OMD   0.0487705754992860f
#define LRC   0.01f

// ===== HMMA helpers (validated R13/R14: rel_err within budget) =====
#define MG_LD 40

__device__ __forceinline__ void mma_bf16(float c[4], uint32_t a0, uint32_t a1,
                                         uint32_t a2, uint32_t a3,
                                         uint32_t b0, uint32_t b1){
    asm volatile(
        "mma.sync.aligned.m16n8k16.row.col.f32.bf16.bf16.f32 "
        "{%0,%1,%2,%3}, {%4,%5,%6,%7}, {%8,%9}, {%0,%1,%2,%3};"
        : "+f"(c[0]), "+f"(c[1]), "+f"(c[2]), "+f"(c[3])
        : "r"(a0), "r"(a1), "r"(a2), "r"(a3), "r"(b0), "r"(b1));
}

#define HMMA_FRAG_AND_MMA(Ah, Al, Bh, Bl, cacc, wm, wn, g, t)                        \
    _Pragma("unroll")                                                                 \
    for (int ks = 0; ks < 32; ks += 16){                                              \
        uint32_t ah[4][4], al[4][4];                                                  \
        _Pragma("unroll")                                                             \
        for (int mt=0; mt<4; mt++){                                                   \
            int row = (wm) + mt*16;                                                   \
            int o00 = (row + (g)    )*MG_LD + ks + 2*(t);                             \
            int o10 = (row + (g) + 8)*MG_LD + ks + 2*(t);                             \
            ah[mt][0] = *(const uint32_t*)&Ah[o00];                                   \
            ah[mt][1] = *(const uint32_t*)&Ah[o10];                                   \
            ah[mt][2] = *(const uint32_t*)&Ah[o00 + 8];                               \
            ah[mt][3] = *(const uint32_t*)&Ah[o10 + 8];                               \
            al[mt][0] = *(const uint32_t*)&Al[o00];                                   \
            al[mt][1] = *(const uint32_t*)&Al[o10];                                   \
            al[mt][2] = *(const uint32_t*)&Al[o00 + 8];                               \
            al[mt][3] = *(const uint32_t*)&Al[o10 + 8];                               \
        }                                                                             \
        uint32_t bh[4][2], bl[4][2];                                                  \
        _Pragma("unroll")                                                             \
        for (int nt=0; nt<4; nt++){                                                   \
            int n = (wn) + nt*8 + (g);                                                \
            int o = n*MG_LD + ks + 2*(t);                                             \
            bh[nt][0] = *(const uint32_t*)&Bh[o];                                     \
            bh[nt][1] = *(const uint32_t*)&Bh[o + 8];                                 \
            bl[nt][0] = *(const uint32_t*)&Bl[o];                                     \
            bl[nt][1] = *(const uint32_t*)&Bl[o + 8];                                 \
        }                                                                             \
        _Pragma("unroll")                                                             \
        for (int mt=0; mt<4; mt++)                                                    \
            _Pragma("unroll")                                                         \
            for (int nt=0; nt<4; nt++){                                               \
                mma_bf16(cacc[mt][nt], ah[mt][0],ah[mt][1],ah[mt][2],ah[mt][3], bh[nt][0],bh[nt][1]); \
                mma_bf16(cacc[mt][nt], ah[mt][0],ah[mt][1],ah[mt][2],ah[mt][3], bl[nt][0],bl[nt][1]); \
                mma_bf16(cacc[mt][nt], al[mt][0],al[mt][1],al[mt][2],al[mt][3], bh[nt][0],bh[nt][1]); \
            }                                                                         \
    }

__device__ __forceinline__ void split_store(unsigned short* H, unsigned short* L,
                                            int off, float v){
    __nv_bfloat16 h = __float2bfloat16(v);
    __nv_bfloat16 l = __float2bfloat16(v - __bfloat162float(h));
    H[off] = __bfloat16_as_ushort(h);
    L[off] = __bfloat16_as_ushort(l);
}

// ---------------------------------------------------------------------------
// Kernel 1: SGEMM on HMMA  C[m][n] = sum_k x[m][k]*W[n][k]
// ---------------------------------------------------------------------------
__global__ __launch_bounds__(256) void sgemm_mma(const float* __restrict__ A,
                                                 const float* __restrict__ W)
{
    __shared__ unsigned short Ah[128*MG_LD], Al[128*MG_LD];
    __shared__ unsigned short Bh[128*MG_LD], Bl[128*MG_LD];
    const int tid = threadIdx.x;
    const int wid = tid >> 5, lane = tid & 31;
    const int g = lane >> 2, t = lane & 3;
    const int n0 = blockIdx.x * 128;
    const int m0 = blockIdx.y * 128;
    const int wm = (wid >> 2) * 64;
    const int wn = (wid & 3) * 32;

    float c[4][4][4];
    #pragma unroll
    for (int i=0;i<4;i++)
        #pragma unroll
        for (int j=0;j<4;j++)
            #pragma unroll
            for (int q=0;q<4;q++) c[i][j][q]=0.f;

    for (int k0 = 0; k0 < NI; k0 += 32){
        #pragma unroll
        for (int i = 0; i < 16; i++){
            int idx = tid + i*256;          // k fast (coalesced)
            int k = idx & 31, m = idx >> 5;
            split_store(Ah, Al, m*MG_LD + k, __ldg(A + (size_t)(m0+m)*NI + k0 + k));
            split_store(Bh, Bl, m*MG_LD + k, __ldg(W + (size_t)(n0+m)*NI + k0 + k));
        }
        __syncthreads();
        HMMA_FRAG_AND_MMA(Ah, Al, Bh, Bl, c, wm, wn, g, t)
        __syncthreads();
    }

    #pragma unroll
    for (int mt=0; mt<4; mt++){
        int row = m0 + wm + mt*16 + g;
        #pragma unroll
        for (int nt=0; nt<4; nt++){
            int n = n0 + wn + nt*8 + 2*t;
            float* o0 = g_C + (size_t)row*N2H + n;
            float* o1 = o0 + 8*N2H;
            o0[0] = c[mt][nt][0];  o0[1] = c[mt][nt][1];
            o1[0] = c[mt][nt][2];  o1[1] = c[mt][nt][3];
        }
    }
}

// ---------------------------------------------------------------------------
// Kernel 2: per-(b,h) sequential traces: keys = tanh(ks), kt' = d*kt' + key
// ---------------------------------------------------------------------------
__global__ __launch_bounds__(256) void tracek_kernel(float* __restrict__ keys_out)
{
    int gid = blockIdx.x*blockDim.x + threadIdx.x;
    int b = gid >> 9, h = gid & 511;
    const float* c = g_C + (size_t)b*NS*N2H + h;
    float* ko = keys_out + (size_t)b*NS*NHH + h;
    float* kp = g_KTP    + (size_t)b*NS*NHH + h;
    float ks = 0.f, kt = 0.f;
    #pragma unroll 8
    for (int t=0;t<NS;t++){
        ks = fmaf(ks, ALPHA, __ldg(c + (size_t)t*N2H));
        float k = fast_tanh(ks);
        ko[(size_t)t*NHH] = k;
        kt = fmaf(kt, DECAY, k);
        kp[(size_t)t*NHH] = kt;
    }
}

// ---------------------------------------------------------------------------
// Kernel 3: batched Gram on HMMA (3 tiles, lower-left s>t block never read)
// ---------------------------------------------------------------------------
__global__ __launch_bounds__(256) void gram_mma(const float* __restrict__ keys)
{
    __shared__ unsigned short Ah[128*MG_LD], Al[128*MG_LD];
    __shared__ unsigned short Bh[128*MG_LD], Bl[128*MG_LD];
    const int tid = threadIdx.x;
    const int wid = tid >> 5, lane = tid & 31;
    const int g = lane >> 2, t = lane & 3;
    const int b  = blockIdx.y;
    const int bi = blockIdx.x;           // 0,1,2 -> (0,0),(1,0),(1,1)
    const int bx = (bi >= 1) ? 1 : 0;
    const int by = (bi == 2) ? 1 : 0;
    const int m0 = by * 128;
    const int n0 = bx * 128;
    const float* Ag = g_KTP + (size_t)b*NS*NHH;
    const float* Bg = keys  + (size_t)b*NS*NHH;
    const int wm = (wid >> 2) * 64;
    const int wn = (wid & 3) * 32;

    float c[4][4][4];
    #pragma unroll
    for (int i=0;i<4;i++)
        #pragma unroll
        for (int j=0;j<4;j++)
            #pragma unroll
            for (int q=0;q<4;q++) c[i][j][q]=0.f;

    for (int k0 = 0; k0 < NHH; k0 += 32){
        #pragma unroll
        for (int i = 0; i < 16; i++){
            int idx = tid + i*256;
            int k = idx & 31, m = idx >> 5;
            split_store(Ah, Al, m*MG_LD + k, __ldg(Ag + (size_t)(m0+m)*NHH + k0 + k));
            split_store(Bh, Bl, m*MG_LD + k, __ldg(Bg + (size_t)(n0+m)*NHH + k0 + k));
        }
        __syncthreads();
        HMMA_FRAG_AND_MMA(Ah, Al, Bh, Bl, c, wm, wn, g, t)
        __syncthreads();
    }

    float* Gout = g_G + (size_t)b*NS*NS;
    #pragma unroll
    for (int mt=0; mt<4; mt++){
        int row = m0 + wm + mt*16 + g;
        #pragma unroll
        for (int nt=0; nt<4; nt++){
            int n = n0 + wn + nt*8 + 2*t;
            float* o0 = Gout + (size_t)row*NS + n;
            float* o1 = o0 + 8*NS;
            o0[0] = c[mt][nt][0];  o0[1] = c[mt][nt][1];
            o1[0] = c[mt][nt][2];  o1[1] = c[mt][nt][3];
        }
    }
}

// ---------------------------------------------------------------------------
// Kernel 4: base GEMM for chunk c (c>=1)
// ---------------------------------------------------------------------------
__global__ __launch_bounds__(256) void basegemm_kernel(int c)
{
    __shared__ float As[32][64+1];
    __shared__ float Bs[32][64+1];
    const int tid = threadIdx.x;
    const int r0 = blockIdx.x * 64;
    const int b  = blockIdx.y;
    const int ty = tid >> 4, tx = tid & 15;
    const int tcol0 = c*CS;
    float acc[4][4];
    #pragma unroll
    for (int i=0;i<4;i++)
        #pragma unroll
        for (int j=0;j<4;j++) acc[i][j]=0.f;
    const int K = c*CS;
    for (int k0=0; k0<K; k0+=32){
        #pragma unroll
        for (int i=0;i<8;i++){
            int idx = tid + i*256;
            int kk = idx >> 6, col = idx & 63;
            As[kk][col] = g_WQ[((size_t)b*NS + k0+kk)*NHH + r0 + col];
            Bs[kk][col] = g_G [((size_t)b*NS + k0+kk)*NS  + tcol0 + col];
        }
        __syncthreads();
        #pragma unroll
        for (int kk=0;kk<32;kk++){
            float a[4], bb[4];
            #pragma unroll
            for (int i=0;i<4;i++) a[i]  = As[kk][ty*4+i];
            #pragma unroll
            for (int j=0;j<4;j++) bb[j] = Bs[kk][tx*4+j];
            #pragma unroll
            for (int i=0;i<4;i++)
                #pragma unroll
                for (int j=0;j<4;j++)
                    acc[i][j] = fmaf(a[i], bb[j], acc[i][j]);
        }
        __syncthreads();
    }
    #pragma unroll
    for (int i=0;i<4;i++)
        #pragma unroll
        for (int j=0;j<4;j++)
            g_BASE[((size_t)b*NHH + r0 + ty*4 + i)*CS + tx*4 + j] = acc[i][j];
}

// ---------------------------------------------------------------------------
// Kernel 5: chunk scan — EXACT R13 version (28us measured). Outer loop FULLY
// UNROLLED so acc[] stays in registers (dropping the pragma spilled acc to
// local memory and tripled runtime in R14).
// ---------------------------------------------------------------------------
__global__ __launch_bounds__(256) void scan_kernel(int c, float* __restrict__ vals_out)
{
    __shared__ float Gs[CS][CS+1];
    const int tid = threadIdx.x;
    const int rh  = blockIdx.x;
    const int b   = blockIdx.y;
    const int r   = rh*256 + tid;

    for (int idx = tid; idx < CS*CS; idx += 256){
        int j = idx >> 6, j2 = idx & 63;
        Gs[j][j2] = g_G[((size_t)b*NS + c*CS + j)*NS + c*CS + j2];
    }
    __syncthreads();

    float vs, vt, P, Q;
    if (c == 0){ vs=0.f; vt=0.f; P=1.f; Q=LRC*OMD; }
    else { vs=g_SVS[b*NHH+r]; vt=g_SVT[b*NHH+r]; P=g_SP[b*NHH+r]; Q=g_SQ[b*NHH+r]; }

    float acc[CS];
    #pragma unroll
    for (int j=0;j<CS;j++) acc[j]=0.f;

    const float* ivp = g_C + ((size_t)(b*NS + c*CS))*N2H + NHH + r;
    const float* bp  = g_BASE + ((size_t)b*NHH + r)*CS;
    float* vp  = vals_out + ((size_t)(b*NS + c*CS))*NHH + r;
    float* wqp = g_WQ     + ((size_t)(b*NS + c*CS))*NHH + r;

    #pragma unroll
    for (int j=0;j<CS;j++){
        float base = 0.f;
        if (c > 0) base = __ldg(bp + j);
        float iv = __ldg(ivp + (size_t)j*N2H);
        float dotraw = acc[j] + base;
        float dtrue = P * dotraw;
        vs = fmaf(vs, ALPHA, fmaf(0.2f, dtrue, iv));
        float v = tanh_approx(vs);
        vp[(size_t)j*NHH] = v;
        vt = fmaf(OMD, v, DECAY*vt);
        float e = LRC*vt*vt;
        P *= (1.0f - e);
        Q *= fmaf(e, fmaf(e, 1.0f + e, 1.0f), 1.0f);
        float wq = Q*vt;
        wqp[(size_t)j*NHH] = wq;
        #pragma unroll
        for (int j2=j+1;j2<CS;j2++)
            acc[j2] = fmaf(wq, Gs[j][j2], acc[j2]);
    }

    g_SVS[b*NHH+r]=vs; g_SVT[b*NHH+r]=vt; g_SP[b*NHH+r]=P; g_SQ[b*NHH+r]=Q;
}

// ---------------------------------------------------------------------------
// Kernel 6: final mem GEMM on HMMA (unchanged, validated R13)
// ---------------------------------------------------------------------------
__global__ __launch_bounds__(256) void memgemm_mma(float* __restrict__ mem_out)
{
    __shared__ unsigned short Ah[128*MG_LD], Al[128*MG_LD];
    __shared__ unsigned short Bh[128*MG_LD], Bl[128*MG_LD];

    const int tid = threadIdx.x;
    const int wid = tid >> 5, lane = tid & 31;
    const int g = lane >> 2, t = lane & 3;
    const int n0 = blockIdx.x * 128;
    const int r0 = blockIdx.y * 128;
    const int b  = blockIdx.z;
    const int wm = (wid >> 2) * 64;
    const int wn = (wid & 3) * 32;

    float c[4][4][4];
    #pragma unroll
    for (int i=0;i<4;i++)
        #pragma unroll
        for (int j=0;j<4;j++)
            #pragma unroll
            for (int q=0;q<4;q++) c[i][j][q]=0.f;

    for (int k0 = 0; k0 < NS; k0 += 32){
        #pragma unroll
        for (int i = 0; i < 16; i++){
            int idx = tid + i*256;          // m fast (operands k-major)
            int m = idx & 127, k = idx >> 7;
            split_store(Ah, Al, m*MG_LD + k, __ldg(g_WQ  + ((size_t)b*NS + k0 + k)*NHH + r0 + m));
            split_store(Bh, Bl, m*MG_LD + k, __ldg(g_KTP + ((size_t)b*NS + k0 + k)*NHH + n0 + m));
        }
        __syncthreads();
        HMMA_FRAG_AND_MMA(Ah, Al, Bh, Bl, c, wm, wn, g, t)
        __syncthreads();
    }

    #pragma unroll
    for (int mt=0; mt<4; mt++){
        int row0g = r0 + wm + mt*16 + g;
        float p0 = g_SP[b*NHH + row0g];
        float p1 = g_SP[b*NHH + row0g + 8];
        #pragma unroll
        for (int nt=0; nt<4; nt++){
            int n = n0 + wn + nt*8 + 2*t;
            float* o0 = mem_out + ((size_t)b*NHH + row0g)*NHH + n;
            float* o1 = o0 + 8*NHH;
            o0[0] = c[mt][nt][0]*p0;  o0[1] = c[mt][nt][1]*p0;
            o1[0] = c[mt][nt][2]*p1;  o1[1] = c[mt][nt][3]*p1;
        }
    }
}

// ---------------------------------------------------------------------------
extern "C" void kernel_launch(void* const* d_in, const int* in_sizes, int n_in,
                              void* d_out, int out_size)
{
    const float* x = (const float*)d_in[0];   // [64,256,256]
    const float* W = (const float*)d_in[1];   // [1024,256]
    float* out = (float*)d_out;
    float* mem_out  = out;                                    // [64,512,512]
    float* keys_out = out + (size_t)NB*NHH*NHH;               // [64,256,512]
    float* vals_out = keys_out + (size_t)NB*NS*NHH;           // [64,256,512]

    sgemm_mma<<<dim3(N2H/128, NM/128), 256>>>(x, W);          // (8,128)
    tracek_kernel<<<(NB*NHH)/256, 256>>>(keys_out);
    gram_mma<<<dim3(3, NB), 256>>>(keys_out);
    for (int c = 0; c < NC; c++){
        if (c > 0) basegemm_kernel<<<dim3(NHH/64, NB), 256>>>(c);
        scan_kernel<<<dim3(2, NB), 256>>>(c, vals_out);
    }
    memgemm_mma<<<dim3(4, 4, NB), 256>>>(mem_out);
}